// round 15
// baseline (speedup 1.0000x reference)
#include <cuda_runtime.h>
#include <cstdint>

typedef unsigned long long ull;

#define NPTS  10000
#define NPAD  10016
#define DDIM  3072
#define NSLOT 8
#define UNITS 7584
#define GRID1 296

__device__ __align__(16) float g_cp[NSLOT * 16 * NPAD];
__device__ __align__(16) float g_ip[NSLOT * NPAD];
__device__ __align__(16) float g_lg[16 * NPAD];
__device__ __align__(16) float g_w [NPAD * 16];
__device__ __align__(16) float g_mp[4 * 16 * DDIM];
__device__ __align__(16) float g_xt[DDIM * 16];
__device__ float g_pmax[16 * 8];
__device__ float g_psum[16 * 128];
__device__ float g_c[4];
__device__ unsigned g_barc;

__device__ __forceinline__ ull dup2(float v) {
    ull r; asm("mov.b64 %0, {%1, %1};" : "=l"(r) : "f"(v)); return r;
}
__device__ __forceinline__ void fma2(ull& d, ull a, ull b) {
    asm("fma.rn.f32x2 %0, %1, %2, %0;" : "+l"(d) : "l"(a), "l"(b));
}
__device__ __forceinline__ void unpack2(ull v, float& lo, float& hi) {
    asm("mov.b64 {%0, %1}, %2;" : "=f"(lo), "=f"(hi) : "l"(v));
}
__device__ __forceinline__ void cpa16(uint32_t d, const float* s) {
    asm volatile("cp.async.ca.shared.global [%0], [%1], 16;" :: "r"(d), "l"(s));
}
__device__ __forceinline__ void cpa16z(uint32_t d, const float* s, int sz) {
    asm volatile("cp.async.ca.shared.global [%0], [%1], 16, %2;" :: "r"(d), "l"(s), "r"(sz));
}
#define CPCOMMIT() asm volatile("cp.async.commit_group;")
#define CPWAIT(n)  asm volatile("cp.async.wait_group %0;" :: "n"(n) : "memory")

// ---- L0: zero slots + constants ----
__global__ __launch_bounds__(256) void kz(const float* __restrict__ sval) {
    int i = blockIdx.x * 256 + threadIdx.x;
    float4 z = make_float4(0.f, 0.f, 0.f, 0.f);
    const int c4 = NSLOT * 16 * NPAD / 4;
    const int i4 = NSLOT * NPAD / 4;
    for (int j = i; j < c4; j += 148 * 256) ((float4*)g_cp)[j] = z;
    for (int j = i; j < i4; j += 148 * 256) ((float4*)g_ip)[j] = z;
    if (i == 0) {
        float s = sval[0];
        float at = sqrtf(1.f - s);
        g_c[0] = at; g_c[1] = s;
        g_c[2] = at / s;
        g_c[3] = -(at * at) / (2.f * s);
        g_barc = 0u;
    }
}

// ---- L1/L2: transpose x ----
__global__ __launch_bounds__(256) void ktr(const float* __restrict__ x, int off) {
    int i = off + blockIdx.x * 256 + threadIdx.x;
    if (i < DDIM * 16) {
        int b = i & 15, k = i >> 4;
        g_xt[i] = x[b * DDIM + k];
    }
}

// ---- k1 flush: reduce acc over kp, store to slot ----
__device__ __forceinline__ void flushk1(ull (&acc)[4][8], float (&isq)[4],
                                        float2* red2, int t, int n_g, int kp,
                                        int tile, int slot) {
    const int n0 = tile * 128;
#pragma unroll 1
    for (int bp = 0; bp < 8; bp++) {
        __syncthreads();
#pragma unroll
        for (int r = 0; r < 4; r++) {
            float lo2, hi2; unpack2(acc[r][bp], lo2, hi2);
            red2[(kp * 32 + n_g) * 4 + r] = make_float2(lo2, hi2);
        }
        __syncthreads();
        if (t < 128) {
            const int ng2 = t & 31, r2 = t >> 5;
            float sx = 0.f, sy = 0.f;
#pragma unroll
            for (int q = 0; q < 8; q++) {
                float2 v = red2[(q * 32 + ng2) * 4 + r2];
                sx += v.x; sy += v.y;
            }
            int n = n0 + t;
            if (n < NPTS) {
                g_cp[(slot * 16 + 2 * bp) * NPAD + n] = sx;
                g_cp[(slot * 16 + 2 * bp + 1) * NPAD + n] = sy;
            }
        }
    }
    __syncthreads();
    {
        float* rf = (float*)red2;
#pragma unroll
        for (int r = 0; r < 4; r++) rf[(kp * 32 + n_g) * 4 + r] = isq[r];
    }
    __syncthreads();
    if (t < 128) {
        const float* rf2 = (const float*)red2;
        const int ng2 = t & 31, r2 = t >> 5;
        float s = 0.f;
#pragma unroll
        for (int q = 0; q < 8; q++) s += rf2[(q * 32 + ng2) * 4 + r2];
        int n = tile * 128 + t;
        if (n < NPTS) g_ip[slot * NPAD + n] = s;
    }
    __syncthreads();
}

// ---- L3: k1 v3 — 296 persistent CTAs, flat split of 7584 chunk-units ----
// unit u: tile = u/96 (128 n), ch = u%96 (32 k). Thread (n_g=t&31, kp=t>>5):
// rows n_g+32r (r<4), k = kp*4..+3 per chunk. slot = c&7 (<=5 CTAs/tile).
__global__ __launch_bounds__(256, 2) void k1(const float* __restrict__ img) {
    __shared__ float si[2][128 * 32];
    __shared__ float xs[2][32 * 16];
    __shared__ float2 red2[1024];

    const int t = threadIdx.x, c = blockIdx.x;
    const int lo = c * UNITS / GRID1, hi = (c + 1) * UNITS / GRID1;
    const int slot = c & 7;
    const int n_g = t & 31, kp = t >> 5;
    const int lr0 = t >> 3, lc4 = t & 7;
    const int swc = ((lc4 ^ (lr0 & 7)) << 2);
    const int pcol = ((kp ^ (n_g & 7)) << 2);
    const uint32_t usi0 = (uint32_t)__cvta_generic_to_shared(si[0]);
    const uint32_t usi1 = (uint32_t)__cvta_generic_to_shared(si[1]);
    const uint32_t uxs0 = (uint32_t)__cvta_generic_to_shared(xs[0]);
    const uint32_t uxs1 = (uint32_t)__cvta_generic_to_shared(xs[1]);

    ull acc[4][8];
    float isq[4] = {0.f, 0.f, 0.f, 0.f};
#pragma unroll
    for (int r = 0; r < 4; r++)
#pragma unroll
        for (int bp = 0; bp < 8; bp++) acc[r][bp] = 0ULL;

    // stage unit u into ring stage st
    auto stage = [&](int u, int st) {
        const int tl = u / 96, ch = u - tl * 96;
        const int kk = ch * 32;
        const uint32_t ub = st ? usi1 : usi0;
        const uint32_t ux = st ? uxs1 : uxs0;
#pragma unroll
        for (int j = 0; j < 4; j++) {
            int row = tl * 128 + lr0 + 32 * j;
            int sz = (row < NPTS) ? 16 : 0;
            const float* src = img + (size_t)min(row, NPTS - 1) * DDIM + kk + lc4 * 4;
            cpa16z(ub + (uint32_t)(((lr0 + 32 * j) * 32 + swc) * 4), src, sz);
        }
        if (t < 128) cpa16z(ux + (uint32_t)(t * 16), g_xt + (size_t)kk * 16 + t * 4, 16);
    };

    int cur = lo / 96;
    stage(lo, lo & 1);
    CPCOMMIT();

    for (int u = lo; u < hi; u++) {
        const int tl = u / 96;
        if (tl != cur) {
            flushk1(acc, isq, red2, t, n_g, kp, cur, slot);
#pragma unroll
            for (int r = 0; r < 4; r++) {
#pragma unroll
                for (int bp = 0; bp < 8; bp++) acc[r][bp] = 0ULL;
                isq[r] = 0.f;
            }
            cur = tl;
        }
        if (u + 1 < hi) stage(u + 1, (u + 1) & 1);
        CPCOMMIT();
        CPWAIT(1);
        __syncthreads();
        const float* sif = si[u & 1];
        const float* xsf = xs[u & 1];
        float4 iv[4];
#pragma unroll
        for (int r = 0; r < 4; r++)
            iv[r] = *(const float4*)&sif[(n_g + 32 * r) * 32 + pcol];
#pragma unroll
        for (int kk2 = 0; kk2 < 4; kk2++) {
            const ulonglong2* xr = (const ulonglong2*)(xsf + (kp * 4 + kk2) * 16);
            ulonglong2 u0 = xr[0], u1 = xr[1], u2 = xr[2], u3 = xr[3];
#pragma unroll
            for (int r = 0; r < 4; r++) {
                float f = (&iv[r].x)[kk2];
                isq[r] = fmaf(f, f, isq[r]);
                ull dv = dup2(f);
                fma2(acc[r][0], u0.x, dv); fma2(acc[r][1], u0.y, dv);
                fma2(acc[r][2], u1.x, dv); fma2(acc[r][3], u1.y, dv);
                fma2(acc[r][4], u2.x, dv); fma2(acc[r][5], u2.y, dv);
                fma2(acc[r][6], u3.x, dv); fma2(acc[r][7], u3.y, dv);
            }
        }
        __syncthreads();
    }
    flushk1(acc, isq, red2, t, n_g, kp, cur, slot);
}

// ---- sm — fused softmax (128 CTAs, grid barrier), 8 slots ----
__global__ __launch_bounds__(256) void sm() {
    const int t = threadIdx.x, c = blockIdx.x;
    __shared__ float wm[8];
    {
        const int b = c >> 3, seg = c & 7;
        const float c1 = g_c[2], c2 = g_c[3];
        const int nbase = seg * 1252;
        const int nend = min(nbase + 1252, NPTS);
        float m = -1e30f;
        for (int i = nbase + t; i < nend; i += 256) {
            float cr = 0.f, qq = 0.f;
#pragma unroll
            for (int s2 = 0; s2 < NSLOT; s2++) {
                cr += g_cp[(s2 * 16 + b) * NPAD + i];
                qq += g_ip[s2 * NPAD + i];
            }
            float lg = fmaf(c1, cr, c2 * qq);
            g_lg[b * NPAD + i] = lg;
            m = fmaxf(m, lg);
        }
        for (int o = 16; o; o >>= 1) m = fmaxf(m, __shfl_xor_sync(0xffffffffu, m, o));
        if ((t & 31) == 0) wm[t >> 5] = m;
        __syncthreads();
        if (t == 0) {
            float v = wm[0];
            for (int w = 1; w < 8; w++) v = fmaxf(v, wm[w]);
            g_pmax[c] = v;
        }
    }
    __syncthreads();
    if (t == 0) {
        __threadfence();
        atomicAdd(&g_barc, 1u);
        while (atomicAdd(&g_barc, 0u) < 128u) {}
    }
    __syncthreads();
    __threadfence();
    {
        const int bb = t & 15, nn = t >> 4;
        const float L2E = 1.44269504088896340736f;
        float M = g_pmax[bb * 8];
#pragma unroll
        for (int s = 1; s < 8; s++) M = fmaxf(M, g_pmax[bb * 8 + s]);
        const int base = c * 79;
        float sum = 0.f;
#pragma unroll
        for (int r = 0; r < 5; r++) {
            int n = base + nn + 16 * r;
            if (n < base + 79 && n < NPTS) {
                float e = exp2f((g_lg[bb * NPAD + n] - M) * L2E);
                g_w[n * 16 + bb] = e;
                sum += e;
            }
        }
        sum += __shfl_xor_sync(0xffffffffu, sum, 16);
        __shared__ float smb[8 * 16];
        if ((t & 31) < 16) smb[(t >> 5) * 16 + bb] = sum;
        __syncthreads();
        if (t < 16) {
            float s = 0.f;
            for (int w = 0; w < 8; w++) s += smb[w * 16 + t];
            g_psum[t * 128 + c] = s;
        }
    }
}

// ---- k3 (R11-proven): cp.async img+w rings, depth 4 ----
__global__ __launch_bounds__(256, 3) void k3(const float* __restrict__ img) {
    __shared__ float si[4][1024];
    __shared__ float sw[4][512];
    __shared__ float red[256 * 8];
    const int t = threadIdx.x, c = blockIdx.x;
    const int dtile = c >> 2, quarter = c & 3;
    const int dt = t & 7, bh = (t >> 3) & 1, p = t >> 4;
    const int q0 = quarter * 2500;
    const uint32_t ui = (uint32_t)__cvta_generic_to_shared(si);
    const uint32_t uw = (uint32_t)__cvta_generic_to_shared(sw);
    const uint32_t di = (uint32_t)(((t >> 3) * 32 + (t & 7) * 4) * 4);
    const float* isrc = img + (size_t)(q0 + (t >> 3)) * DDIM + dtile * 32 + (t & 7) * 4;
    const float* wsrc = g_w + (size_t)q0 * 16 + t * 4;

    ull acc[4][4];
#pragma unroll
    for (int i = 0; i < 4; i++)
#pragma unroll
        for (int j = 0; j < 4; j++) acc[i][j] = 0ULL;

#pragma unroll
    for (int m = 0; m < 3; m++) {
        cpa16(ui + (uint32_t)(m * 4096) + di, isrc + (size_t)(32 * m) * DDIM);
        if (t < 128) cpa16(uw + (uint32_t)(m * 2048 + t * 16), wsrc + 32 * m * 16);
        CPCOMMIT();
    }

#pragma unroll 1
    for (int m = 0; m < 78; m++) {
        CPWAIT(2);
        __syncthreads();
        if (m + 3 < 78) {
            const int m3 = m + 3;
            cpa16(ui + (uint32_t)((m3 & 3) * 4096) + di, isrc + (size_t)(32 * m3) * DDIM);
            if (t < 128) cpa16(uw + (uint32_t)((m3 & 3) * 2048 + t * 16), wsrc + (size_t)(32 * m3) * 16);
        }
        CPCOMMIT();
        const float* sif = si[m & 3];
        const float* swf = sw[m & 3];
        float4 i1 = *(const float4*)&sif[p * 32 + dt * 4];
        float4 i2 = *(const float4*)&sif[(p + 16) * 32 + dt * 4];
        ulonglong2 wa1 = *(const ulonglong2*)&swf[p * 16 + bh * 8];
        ulonglong2 wb1 = *(const ulonglong2*)&swf[p * 16 + bh * 8 + 4];
        ulonglong2 wa2 = *(const ulonglong2*)&swf[(p + 16) * 16 + bh * 8];
        ulonglong2 wb2 = *(const ulonglong2*)&swf[(p + 16) * 16 + bh * 8 + 4];
#pragma unroll
        for (int d = 0; d < 4; d++) {
            ull dv = dup2((&i1.x)[d]);
            fma2(acc[0][d], wa1.x, dv);
            fma2(acc[1][d], wa1.y, dv);
            fma2(acc[2][d], wb1.x, dv);
            fma2(acc[3][d], wb1.y, dv);
        }
#pragma unroll
        for (int d = 0; d < 4; d++) {
            ull dv = dup2((&i2.x)[d]);
            fma2(acc[0][d], wa2.x, dv);
            fma2(acc[1][d], wa2.y, dv);
            fma2(acc[2][d], wb2.x, dv);
            fma2(acc[3][d], wb2.y, dv);
        }
    }
    if (p < 4) {
        int n = q0 + 2496 + p;
        const int dbase = dtile * 32 + dt * 4;
        float4 i1 = *(const float4*)(img + (size_t)n * DDIM + dbase);
        ulonglong2 wa = *(const ulonglong2*)(g_w + (size_t)n * 16 + bh * 8);
        ulonglong2 wbt = *(const ulonglong2*)(g_w + (size_t)n * 16 + bh * 8 + 4);
#pragma unroll
        for (int d = 0; d < 4; d++) {
            ull dv = dup2((&i1.x)[d]);
            fma2(acc[0][d], wa.x, dv);
            fma2(acc[1][d], wa.y, dv);
            fma2(acc[2][d], wbt.x, dv);
            fma2(acc[3][d], wbt.y, dv);
        }
    }

#pragma unroll 1
    for (int bp = 0; bp < 4; bp++) {
        __syncthreads();
#pragma unroll
        for (int d = 0; d < 4; d++) {
            float lo, hi; unpack2(acc[bp][d], lo, hi);
            red[t * 8 + 2 * d] = lo;
            red[t * 8 + 2 * d + 1] = hi;
        }
        __syncthreads();
        if (t < 128) {
            int h = t & 1, d = (t >> 1) & 3, dtw = (t >> 3) & 7, bhw = t >> 6;
            float s = 0.f;
#pragma unroll
            for (int p2 = 0; p2 < 16; p2++)
                s += red[(dtw + bhw * 8 + p2 * 16) * 8 + 2 * d + h];
            int b = bhw * 8 + bp * 2 + h;
            g_mp[(quarter * 16 + b) * DDIM + dtile * 32 + dtw * 4 + d] = s;
        }
    }
}

// ---- k4 ----
__global__ __launch_bounds__(256) void k4(const float* __restrict__ x,
                                          float* __restrict__ out) {
    const int t = threadIdx.x, c = blockIdx.x;
    const int blo = (c * 1024) / DDIM;
    const int bhi = ((c + 1) * 1024 - 1) / DDIM;
    __shared__ float wsum[8];
    __shared__ float invs[2];
    {
        int myb = (t < 128) ? blo : bhi;
        float s = g_psum[myb * 128 + (t & 127)];
        for (int o = 16; o; o >>= 1) s += __shfl_xor_sync(0xffffffffu, s, o);
        if ((t & 31) == 0) wsum[t >> 5] = s;
    }
    __syncthreads();
    if (t == 0)   invs[0] = 1.f / (wsum[0] + wsum[1] + wsum[2] + wsum[3]);
    if (t == 128) invs[1] = 1.f / (wsum[4] + wsum[5] + wsum[6] + wsum[7]);
    __syncthreads();

    const float at = g_c[0], bt2 = g_c[1];
    int i = (c * 256 + t) * 4;
    int b = i / DDIM;
    int d = i - b * DDIM;
    float inv = (b == blo) ? invs[0] : invs[1];
    float4 m0 = *(const float4*)(g_mp + (size_t)b * DDIM + d);
    float4 m1 = *(const float4*)(g_mp + (size_t)(16 + b) * DDIM + d);
    float4 m2 = *(const float4*)(g_mp + (size_t)(32 + b) * DDIM + d);
    float4 m3 = *(const float4*)(g_mp + (size_t)(48 + b) * DDIM + d);
    float4 xv = *(const float4*)(x + i);
    float sc = at * inv / bt2;
    float4 o;
    o.x = sc * (m0.x + m1.x + m2.x + m3.x) - xv.x / bt2;
    o.y = sc * (m0.y + m1.y + m2.y + m3.y) - xv.y / bt2;
    o.z = sc * (m0.z + m1.z + m2.z + m3.z) - xv.z / bt2;
    o.w = sc * (m0.w + m1.w + m2.w + m3.w) - xv.w / bt2;
    *(float4*)(out + i) = o;
}

extern "C" void kernel_launch(void* const* d_in, const int* in_sizes, int n_in,
                              void* d_out, int out_size) {
    const float* x    = (const float*)d_in[0];
    const float* img  = (const float*)d_in[1];
    const float* sval = (const float*)d_in[2];
    float* out = (float*)d_out;

    kz<<<148, 256>>>(sval);        // 0
    ktr<<<96, 256>>>(x, 0);        // 1
    ktr<<<96, 256>>>(x, 24576);    // 2
    k1<<<GRID1, 256>>>(img);       // 3  <- capture lands on new k1
    sm<<<128, 256>>>();            // 4
    k3<<<384, 256>>>(img);         // 5
    k4<<<48, 256>>>(x, out);       // 6
}